// round 5
// baseline (speedup 1.0000x reference)
#include <cuda_runtime.h>
#include <cuda_bf16.h>
#include <cstdint>
#include <cstddef>

#define B_   64
#define S_   512
#define E_   300
#define EP_  304
#define M_   32768

__device__ float g_x[M_ * EP_];            // [S,B,EP], row m=s*64+b
__device__ float g_w0pad[2][1024 * EP_];   // padded w_ih_l0{f,b}
__device__ float g_gx0[M_ * 2048];         // layer0 gate inputs [m, dir*1024+g]
__device__ float g_h1 [M_ * 512];          // layer0 out [m, dir*256+j]
__device__ float g_gx1[M_ * 2048];
__device__ float g_h2 [M_ * 512];
__device__ float g_err[M_];

__device__ __forceinline__ float sigm(float x) { return 1.0f / (1.0f + expf(-x)); }

__global__ void gather_kernel(const int* __restrict__ ids, const float* __restrict__ emb) {
    int m = blockIdx.x, s = m >> 6, b = m & 63;
    int id = ids[b * S_ + s];
    const float* src = emb + (size_t)id * E_;
    float* dst = g_x + (size_t)m * EP_;
    for (int e = threadIdx.x; e < EP_; e += blockDim.x)
        dst[e] = (e < E_) ? src[e] : 0.0f;
}

__global__ void padw_kernel(const float* __restrict__ wf, const float* __restrict__ wb) {
    int row = blockIdx.x & 1023, dir = blockIdx.x >> 10;
    const float* src = (dir ? wb : wf) + (size_t)row * E_;
    float* dst = g_w0pad[dir] + (size_t)row * EP_;
    for (int e = threadIdx.x; e < EP_; e += blockDim.x)
        dst[e] = (e < E_) ? src[e] : 0.0f;
}

// C[m, dir*1024+n] = b1[n]+b2[n] + sum_k A[m,k]*W[n,k]
// BM=128,BN=64,BK=16, double-buffered smem, 1 sync/iter.
__global__ void sgemm_kernel(int layer, int dir,
                             const float* __restrict__ Wext,
                             const float* __restrict__ b1,
                             const float* __restrict__ b2) {
    const float* A; const float* W; float* C; int lda, K;
    if (layer == 0) { A = g_x;  lda = EP_; K = EP_; W = g_w0pad[dir]; C = g_gx0; }
    else            { A = g_h1; lda = 512; K = 512; W = Wext;         C = g_gx1; }
    const int coloff = dir << 10;

    __shared__ float As[2][16][132];
    __shared__ float Bs[2][16][68];

    const int tid = threadIdx.x;
    const int m0 = blockIdx.y * 128, n0 = blockIdx.x * 64;
    const int tx = tid & 15, ty = tid >> 4;
    const int arow = tid >> 2, acol = (tid & 3) * 4;

    float acc[8][4];
#pragma unroll
    for (int i = 0; i < 8; ++i)
#pragma unroll
        for (int j = 0; j < 4; ++j) acc[i][j] = 0.0f;

    const int nIter = K >> 4;

    {
        float4 a0 = *(const float4*)(A + (size_t)(m0 + arow)      * lda + acol);
        float4 a1 = *(const float4*)(A + (size_t)(m0 + arow + 64) * lda + acol);
        float4 bv = *(const float4*)(W + (size_t)(n0 + arow)      * lda + acol);
        As[0][acol + 0][arow] = a0.x; As[0][acol + 1][arow] = a0.y;
        As[0][acol + 2][arow] = a0.z; As[0][acol + 3][arow] = a0.w;
        As[0][acol + 0][arow + 64] = a1.x; As[0][acol + 1][arow + 64] = a1.y;
        As[0][acol + 2][arow + 64] = a1.z; As[0][acol + 3][arow + 64] = a1.w;
        Bs[0][acol + 0][arow] = bv.x; Bs[0][acol + 1][arow] = bv.y;
        Bs[0][acol + 2][arow] = bv.z; Bs[0][acol + 3][arow] = bv.w;
    }
    __syncthreads();

    for (int it = 0; it < nIter; ++it) {
        const int cur = it & 1, nxt = cur ^ 1;
        const bool more = (it + 1 < nIter);
        float4 na0, na1, nbv;
        if (more) {
            const int k0 = (it + 1) << 4;
            na0 = *(const float4*)(A + (size_t)(m0 + arow)      * lda + k0 + acol);
            na1 = *(const float4*)(A + (size_t)(m0 + arow + 64) * lda + k0 + acol);
            nbv = *(const float4*)(W + (size_t)(n0 + arow)      * lda + k0 + acol);
        }
#pragma unroll
        for (int k = 0; k < 16; ++k) {
            float av[8], bw[4];
#pragma unroll
            for (int i = 0; i < 8; ++i) av[i] = As[cur][k][ty * 8 + i];
#pragma unroll
            for (int j = 0; j < 4; ++j) bw[j] = Bs[cur][k][tx * 4 + j];
#pragma unroll
            for (int i = 0; i < 8; ++i)
#pragma unroll
                for (int j = 0; j < 4; ++j)
                    acc[i][j] = fmaf(av[i], bw[j], acc[i][j]);
        }
        if (more) {
            As[nxt][acol + 0][arow] = na0.x; As[nxt][acol + 1][arow] = na0.y;
            As[nxt][acol + 2][arow] = na0.z; As[nxt][acol + 3][arow] = na0.w;
            As[nxt][acol + 0][arow + 64] = na1.x; As[nxt][acol + 1][arow + 64] = na1.y;
            As[nxt][acol + 2][arow + 64] = na1.z; As[nxt][acol + 3][arow + 64] = na1.w;
            Bs[nxt][acol + 0][arow] = nbv.x; Bs[nxt][acol + 1][arow] = nbv.y;
            Bs[nxt][acol + 2][arow] = nbv.z; Bs[nxt][acol + 3][arow] = nbv.w;
        }
        __syncthreads();
    }

    const int ng = n0 + tx * 4;
    float bsum[4];
#pragma unroll
    for (int j = 0; j < 4; ++j) bsum[j] = b1[ng + j] + b2[ng + j];
#pragma unroll
    for (int i = 0; i < 8; ++i) {
        int m = m0 + ty * 8 + i;
        float4 o;
        o.x = acc[i][0] + bsum[0]; o.y = acc[i][1] + bsum[1];
        o.z = acc[i][2] + bsum[2]; o.w = acc[i][3] + bsum[3];
        *(float4*)(C + (size_t)m * 2048 + coloff + ng) = o;
    }
}

// ---------------------------------------------------------------------------
// Cluster-based bi-LSTM: grid 128 CTAs, cluster (8,1,1).
// Cluster c: dir = c>>3, batch-group bg = c&7 (batches [8bg, 8bg+8)).
// CTA rank r owns h-dims [32r, 32r+32) = 128 gate rows, W slice in smem.
// Per step: dot over local smem h copy; h exchanged via DSMEM push +
// barrier.cluster (no grid-wide sync anywhere).
// smem floats: Wsl [128][260] @0, Hb [2][8][256] @33280,
//              Gxs [2][8][136] @37376, Gs [8][136] @39552  (total 40640)
#define LSTM_SMEM_BYTES (40640 * 4)

__global__ void __launch_bounds__(256, 1) __cluster_dims__(8, 1, 1)
lstm_kernel(int layer, const float* __restrict__ whh_f,
            const float* __restrict__ whh_b) {
    extern __shared__ float smf[];
    float* Wsl = smf;            // [128][260]
    float* Hb  = smf + 33280;    // [2][8][256]
    float* Gxs = smf + 37376;    // [2][8][136]
    float* Gs  = smf + 39552;    // [8][136]

    const int tid = threadIdx.x;
    uint32_t rank;
    asm("mov.u32 %0, %%cluster_ctarank;" : "=r"(rank));
    const int cid = blockIdx.x >> 3;
    const int dir = cid >> 3;
    const int bg  = cid & 7;
    const int j0  = (int)(rank << 5);

    const float* whh  = dir ? whh_b : whh_f;
    const float* gx   = layer ? g_gx1 : g_gx0;
    float*       hout = layer ? g_h2  : g_h1;

    // Load W slice: local row rloc = q*32+jj -> whh[q*256 + j0 + jj][:]
    {
        int rloc = tid >> 1, half = (tid & 1) << 7;
        int q = rloc >> 5, jj = rloc & 31;
        const float4* src = (const float4*)(whh + (size_t)((q << 8) + j0 + jj) * 256 + half);
        float4* dst = (float4*)(Wsl + rloc * 260 + half);
#pragma unroll
        for (int i = 0; i < 32; ++i) dst[i] = src[i];
    }
    // Zero h_buf[0] (2048 floats)
    {
        float4* hz = (float4*)Hb;
        hz[tid] = make_float4(0.f, 0.f, 0.f, 0.f);
        hz[tid + 256] = make_float4(0.f, 0.f, 0.f, 0.f);
    }
    // gx prefetch mapping: batch pb, gate chunk pq, 4-col group pe
    const int pb = tid >> 5, pw = tid & 31, pq = pw >> 3, pe = pw & 7;
    {   // prefill Gxs[0] for t=0
        int s0 = dir ? 511 : 0;
        float4 gv = *(const float4*)(gx + ((size_t)(s0 * 64 + bg * 8 + pb)) * 2048
                                       + (dir << 10) + (pq << 8) + j0 + (pe << 2));
        *(float4*)(Gxs + pb * 136 + (pq << 5) + (pe << 2)) = gv;
    }
    // DSMEM peer base addresses for Hb
    uint32_t hb_peer[8];
    {
        uint32_t hb_local = (uint32_t)__cvta_generic_to_shared(Hb);
#pragma unroll
        for (int p = 0; p < 8; ++p)
            asm("mapa.shared::cluster.u32 %0, %1, %2;"
                : "=r"(hb_peer[p]) : "r"(hb_local), "r"(p));
    }
    __syncthreads();

    const int tile = tid >> 3, kid = tid & 7;
    const int r0 = tile << 2;
    const int ujj = tid >> 3, ub = tid & 7;     // update mapping
    float creg = 0.0f;

    for (int t = 0; t < 512; ++t) {
        const int s = dir ? (511 - t) : t;
        const int cur = t & 1, nxt = cur ^ 1;

        // prefetch gx(t+1) into regs (off critical path)
        float4 gv;
        {
            int t2 = (t < 511) ? (t + 1) : t;
            int s2 = dir ? (511 - t2) : t2;
            gv = *(const float4*)(gx + ((size_t)(s2 * 64 + bg * 8 + pb)) * 2048
                                    + (dir << 10) + (pq << 8) + j0 + (pe << 2));
        }

        // dot: 4 rows (r0..r0+3) x 8 batches, k-split 8 (kid owns k = 4kid+32kk)
        float acc[4][8];
#pragma unroll
        for (int i = 0; i < 4; ++i)
#pragma unroll
            for (int j = 0; j < 8; ++j) acc[i][j] = 0.0f;

        const float4* wp0 = (const float4*)(Wsl + (r0 + 0) * 260 + (kid << 2));
        const float4* wp1 = (const float4*)(Wsl + (r0 + 1) * 260 + (kid << 2));
        const float4* wp2 = (const float4*)(Wsl + (r0 + 2) * 260 + (kid << 2));
        const float4* wp3 = (const float4*)(Wsl + (r0 + 3) * 260 + (kid << 2));
        const float4* hp  = (const float4*)(Hb + (cur << 11) + (kid << 2));
#pragma unroll
        for (int kk = 0; kk < 8; ++kk) {
            const int ko = kk << 3;
            float4 w0 = wp0[ko], w1 = wp1[ko], w2 = wp2[ko], w3 = wp3[ko];
#pragma unroll
            for (int j = 0; j < 8; ++j) {
                float4 hv = hp[(j << 6) + ko];
                acc[0][j] = fmaf(w0.x, hv.x, fmaf(w0.y, hv.y, fmaf(w0.z, hv.z, fmaf(w0.w, hv.w, acc[0][j]))));
                acc[1][j] = fmaf(w1.x, hv.x, fmaf(w1.y, hv.y, fmaf(w1.z, hv.z, fmaf(w1.w, hv.w, acc[1][j]))));
                acc[2][j] = fmaf(w2.x, hv.x, fmaf(w2.y, hv.y, fmaf(w2.z, hv.z, fmaf(w2.w, hv.w, acc[2][j]))));
                acc[3][j] = fmaf(w3.x, hv.x, fmaf(w3.y, hv.y, fmaf(w3.z, hv.z, fmaf(w3.w, hv.w, acc[3][j]))));
            }
        }
        // reduce across 8 kid lanes; kid 0 writes Gs[b][row]
#pragma unroll
        for (int i = 0; i < 4; ++i)
#pragma unroll
            for (int j = 0; j < 8; ++j) {
                float v = acc[i][j];
                v += __shfl_xor_sync(0xffffffffu, v, 1);
                v += __shfl_xor_sync(0xffffffffu, v, 2);
                v += __shfl_xor_sync(0xffffffffu, v, 4);
                if (kid == 0) Gs[j * 136 + r0 + i] = v;
            }
        // stage gx(t+1)
        *(float4*)(Gxs + nxt * 1088 + pb * 136 + (pq << 5) + (pe << 2)) = gv;
        __syncthreads();

        // update: thread (ujj, ub) owns h-dim j0+ujj, batch ub
        {
            const float* gsb = Gs + ub * 136;
            const float* gxb = Gxs + cur * 1088 + ub * 136;
            float di = gsb[ujj]      + gxb[ujj];
            float df = gsb[32 + ujj] + gxb[32 + ujj];
            float dg = gsb[64 + ujj] + gxb[64 + ujj];
            float dq = gsb[96 + ujj] + gxb[96 + ujj];
            float c = sigm(df) * creg + sigm(di) * tanhf(dg);
            creg = c;
            float h = sigm(dq) * tanhf(c);
            uint32_t off = (uint32_t)(((nxt << 11) + (ub << 8) + j0 + ujj) << 2);
#pragma unroll
            for (int p = 0; p < 8; ++p)
                asm volatile("st.shared::cluster.f32 [%0], %1;"
                             :: "r"(hb_peer[p] + off), "f"(h) : "memory");
            hout[((size_t)(s * 64 + bg * 8 + ub)) * 512 + (dir << 8) + j0 + ujj] = h;
        }
        asm volatile("barrier.cluster.arrive.aligned;" ::: "memory");
        asm volatile("barrier.cluster.wait.aligned;" ::: "memory");
    }
}

__global__ void score_kernel(const float* __restrict__ wlin,
                             const float* __restrict__ blin,
                             const float* __restrict__ labels,
                             const int* __restrict__ masks,
                             float* __restrict__ outs) {
    int w = blockIdx.x * 8 + (threadIdx.x >> 5);
    int lane = threadIdx.x & 31;
    int s = w >> 6, b = w & 63;
    const float* hp = g_h2 + (size_t)w * 512;
    float acc = 0.0f;
#pragma unroll
    for (int j = lane; j < 256; j += 32)
        acc += 0.5f * (hp[j] + hp[256 + j]) * wlin[j];
#pragma unroll
    for (int d = 16; d; d >>= 1) acc += __shfl_xor_sync(0xffffffffu, acc, d);
    if (lane == 0) {
        float sc = sigm(acc + blin[0]);
        int oi = b * S_ + s;
        outs[oi] = sc;
        float df = sc - labels[oi];
        g_err[oi] = df * df * (float)masks[oi];
    }
}

__global__ void loss_kernel(const int* __restrict__ masks,
                            float* __restrict__ out, int out_size) {
    __shared__ float sr[64];
    int b = threadIdx.x;
    if (b < 64) {
        float se = 0.0f, sm = 0.0f;
        for (int s = 0; s < S_; ++s) {
            se += g_err[b * S_ + s];
            sm += (float)masks[b * S_ + s];
        }
        sr[b] = se / sm;
    }
    __syncthreads();
    if (threadIdx.x == 0 && out_size > M_) {
        float t = 0.0f;
        for (int i = 0; i < 64; ++i) t += sr[i];
        out[M_] = t / 64.0f;
    }
}

extern "C" void kernel_launch(void* const* d_in, const int* in_sizes, int n_in,
                              void* d_out, int out_size) {
    const int*   ids    = (const int*)d_in[0];
    const float* labels = (const float*)d_in[1];
    const int*   masks  = (const int*)d_in[2];
    const float* emb    = (const float*)d_in[3];
    const float* wih0f = (const float*)d_in[4];
    const float* whh0f = (const float*)d_in[5];
    const float* bih0f = (const float*)d_in[6];
    const float* bhh0f = (const float*)d_in[7];
    const float* wih0b = (const float*)d_in[8];
    const float* whh0b = (const float*)d_in[9];
    const float* bih0b = (const float*)d_in[10];
    const float* bhh0b = (const float*)d_in[11];
    const float* wih1f = (const float*)d_in[12];
    const float* whh1f = (const float*)d_in[13];
    const float* bih1f = (const float*)d_in[14];
    const float* bhh1f = (const float*)d_in[15];
    const float* wih1b = (const float*)d_in[16];
    const float* whh1b = (const float*)d_in[17];
    const float* bih1b = (const float*)d_in[18];
    const float* bhh1b = (const float*)d_in[19];
    const float* wlin  = (const float*)d_in[20];
    const float* blin  = (const float*)d_in[21];
    float* out = (float*)d_out;

    static bool attr_done = false;
    if (!attr_done) {
        cudaFuncSetAttribute(lstm_kernel, cudaFuncAttributeMaxDynamicSharedMemorySize,
                             LSTM_SMEM_BYTES);
        attr_done = true;
    }

    gather_kernel<<<M_, 128>>>(ids, emb);
    padw_kernel<<<2048, 128>>>(wih0f, wih0b);

    dim3 gg(16, 256);
    sgemm_kernel<<<gg, 256>>>(0, 0, nullptr, bih0f, bhh0f);
    sgemm_kernel<<<gg, 256>>>(0, 1, nullptr, bih0b, bhh0b);

    lstm_kernel<<<128, 256, LSTM_SMEM_BYTES>>>(0, whh0f, whh0b);

    sgemm_kernel<<<gg, 256>>>(1, 0, wih1f, bih1f, bhh1f);
    sgemm_kernel<<<gg, 256>>>(1, 1, wih1b, bih1b, bhh1b);

    lstm_kernel<<<128, 256, LSTM_SMEM_BYTES>>>(1, whh1f, whh1b);

    score_kernel<<<M_ / 8, 256>>>(wlin, blin, labels, masks, out);
    loss_kernel<<<1, 64>>>(masks, out, out_size);
}

// round 6
// speedup vs baseline: 1.0019x; 1.0019x over previous
#include <cuda_runtime.h>
#include <cuda_bf16.h>
#include <cstdint>
#include <cstddef>

#define B_   64
#define S_   512
#define E_   300
#define EP_  304
#define M_   32768

__device__ float g_x[M_ * EP_];            // [S,B,EP], row m=s*64+b
__device__ float g_w0pad[2][1024 * EP_];   // padded w_ih_l0{f,b}
__device__ float g_gx0[M_ * 2048];         // layer0 gate inputs [m, dir*1024+g]
__device__ float g_h1 [M_ * 512];          // layer0 out [m, dir*256+j]
__device__ float g_gx1[M_ * 2048];
__device__ float g_h2 [M_ * 512];
__device__ float g_err[M_];

__device__ __forceinline__ float sigm(float x) { return 1.0f / (1.0f + expf(-x)); }

__global__ void gather_kernel(const int* __restrict__ ids, const float* __restrict__ emb) {
    int m = blockIdx.x, s = m >> 6, b = m & 63;
    int id = ids[b * S_ + s];
    const float* src = emb + (size_t)id * E_;
    float* dst = g_x + (size_t)m * EP_;
    for (int e = threadIdx.x; e < EP_; e += blockDim.x)
        dst[e] = (e < E_) ? src[e] : 0.0f;
}

__global__ void padw_kernel(const float* __restrict__ wf, const float* __restrict__ wb) {
    int row = blockIdx.x & 1023, dir = blockIdx.x >> 10;
    const float* src = (dir ? wb : wf) + (size_t)row * E_;
    float* dst = g_w0pad[dir] + (size_t)row * EP_;
    for (int e = threadIdx.x; e < EP_; e += blockDim.x)
        dst[e] = (e < E_) ? src[e] : 0.0f;
}

// C[m, dir*1024+n] = b1[n]+b2[n] + sum_k A[m,k]*W[n,k]
// BM=128,BN=64,BK=16, double-buffered smem, 1 sync/iter.
__global__ void sgemm_kernel(int layer, int dir,
                             const float* __restrict__ Wext,
                             const float* __restrict__ b1,
                             const float* __restrict__ b2) {
    const float* A; const float* W; float* C; int lda, K;
    if (layer == 0) { A = g_x;  lda = EP_; K = EP_; W = g_w0pad[dir]; C = g_gx0; }
    else            { A = g_h1; lda = 512; K = 512; W = Wext;         C = g_gx1; }
    const int coloff = dir << 10;

    __shared__ float As[2][16][132];
    __shared__ float Bs[2][16][68];

    const int tid = threadIdx.x;
    const int m0 = blockIdx.y * 128, n0 = blockIdx.x * 64;
    const int tx = tid & 15, ty = tid >> 4;
    const int arow = tid >> 2, acol = (tid & 3) * 4;

    float acc[8][4];
#pragma unroll
    for (int i = 0; i < 8; ++i)
#pragma unroll
        for (int j = 0; j < 4; ++j) acc[i][j] = 0.0f;

    const int nIter = K >> 4;

    {
        float4 a0 = *(const float4*)(A + (size_t)(m0 + arow)      * lda + acol);
        float4 a1 = *(const float4*)(A + (size_t)(m0 + arow + 64) * lda + acol);
        float4 bv = *(const float4*)(W + (size_t)(n0 + arow)      * lda + acol);
        As[0][acol + 0][arow] = a0.x; As[0][acol + 1][arow] = a0.y;
        As[0][acol + 2][arow] = a0.z; As[0][acol + 3][arow] = a0.w;
        As[0][acol + 0][arow + 64] = a1.x; As[0][acol + 1][arow + 64] = a1.y;
        As[0][acol + 2][arow + 64] = a1.z; As[0][acol + 3][arow + 64] = a1.w;
        Bs[0][acol + 0][arow] = bv.x; Bs[0][acol + 1][arow] = bv.y;
        Bs[0][acol + 2][arow] = bv.z; Bs[0][acol + 3][arow] = bv.w;
    }
    __syncthreads();

    for (int it = 0; it < nIter; ++it) {
        const int cur = it & 1, nxt = cur ^ 1;
        const bool more = (it + 1 < nIter);
        float4 na0, na1, nbv;
        if (more) {
            const int k0 = (it + 1) << 4;
            na0 = *(const float4*)(A + (size_t)(m0 + arow)      * lda + k0 + acol);
            na1 = *(const float4*)(A + (size_t)(m0 + arow + 64) * lda + k0 + acol);
            nbv = *(const float4*)(W + (size_t)(n0 + arow)      * lda + k0 + acol);
        }
#pragma unroll
        for (int k = 0; k < 16; ++k) {
            float av[8], bw[4];
#pragma unroll
            for (int i = 0; i < 8; ++i) av[i] = As[cur][k][ty * 8 + i];
#pragma unroll
            for (int j = 0; j < 4; ++j) bw[j] = Bs[cur][k][tx * 4 + j];
#pragma unroll
            for (int i = 0; i < 8; ++i)
#pragma unroll
                for (int j = 0; j < 4; ++j)
                    acc[i][j] = fmaf(av[i], bw[j], acc[i][j]);
        }
        if (more) {
            As[nxt][acol + 0][arow] = na0.x; As[nxt][acol + 1][arow] = na0.y;
            As[nxt][acol + 2][arow] = na0.z; As[nxt][acol + 3][arow] = na0.w;
            As[nxt][acol + 0][arow + 64] = na1.x; As[nxt][acol + 1][arow + 64] = na1.y;
            As[nxt][acol + 2][arow + 64] = na1.z; As[nxt][acol + 3][arow + 64] = na1.w;
            Bs[nxt][acol + 0][arow] = nbv.x; Bs[nxt][acol + 1][arow] = nbv.y;
            Bs[nxt][acol + 2][arow] = nbv.z; Bs[nxt][acol + 3][arow] = nbv.w;
        }
        __syncthreads();
    }

    const int ng = n0 + tx * 4;
    float bsum[4];
#pragma unroll
    for (int j = 0; j < 4; ++j) bsum[j] = b1[ng + j] + b2[ng + j];
#pragma unroll
    for (int i = 0; i < 8; ++i) {
        int m = m0 + ty * 8 + i;
        float4 o;
        o.x = acc[i][0] + bsum[0]; o.y = acc[i][1] + bsum[1];
        o.z = acc[i][2] + bsum[2]; o.w = acc[i][3] + bsum[3];
        *(float4*)(C + (size_t)m * 2048 + coloff + ng) = o;
    }
}

// ---------------------------------------------------------------------------
// Cluster-based bi-LSTM: grid 128 CTAs, cluster (8,1,1).
// Cluster c: dir = c>>3, batch-group bg = c&7 (batches [8bg, 8bg+8)).
// CTA rank r owns h-dims [32r, 32r+32) = 128 gate rows, W slice in smem.
// Per step: dot over local smem h copy; h exchanged via DSMEM push +
// barrier.cluster (no grid-wide sync anywhere).
// smem floats: Wsl [128][260] @0, Hb [2][8][256] @33280,
//              Gxs [2][8][136] @37376, Gs [8][136] @39552  (total 40640)
#define LSTM_SMEM_BYTES (40640 * 4)

__global__ void __launch_bounds__(256, 1) __cluster_dims__(8, 1, 1)
lstm_kernel(int layer, const float* __restrict__ whh_f,
            const float* __restrict__ whh_b) {
    extern __shared__ float smf[];
    float* Wsl = smf;            // [128][260]
    float* Hb  = smf + 33280;    // [2][8][256]
    float* Gxs = smf + 37376;    // [2][8][136]
    float* Gs  = smf + 39552;    // [8][136]

    const int tid = threadIdx.x;
    uint32_t rank;
    asm("mov.u32 %0, %%cluster_ctarank;" : "=r"(rank));
    const int cid = blockIdx.x >> 3;
    const int dir = cid >> 3;
    const int bg  = cid & 7;
    const int j0  = (int)(rank << 5);

    const float* whh  = dir ? whh_b : whh_f;
    const float* gx   = layer ? g_gx1 : g_gx0;
    float*       hout = layer ? g_h2  : g_h1;

    // Load W slice: local row rloc = q*32+jj -> whh[q*256 + j0 + jj][:]
    {
        int rloc = tid >> 1, half = (tid & 1) << 7;
        int q = rloc >> 5, jj = rloc & 31;
        const float4* src = (const float4*)(whh + (size_t)((q << 8) + j0 + jj) * 256 + half);
        float4* dst = (float4*)(Wsl + rloc * 260 + half);
#pragma unroll
        for (int i = 0; i < 32; ++i) dst[i] = src[i];
    }
    // Zero h_buf[0] (2048 floats)
    {
        float4* hz = (float4*)Hb;
        hz[tid] = make_float4(0.f, 0.f, 0.f, 0.f);
        hz[tid + 256] = make_float4(0.f, 0.f, 0.f, 0.f);
    }
    // gx prefetch mapping: batch pb, gate chunk pq, 4-col group pe
    const int pb = tid >> 5, pw = tid & 31, pq = pw >> 3, pe = pw & 7;
    {   // prefill Gxs[0] for t=0
        int s0 = dir ? 511 : 0;
        float4 gv = *(const float4*)(gx + ((size_t)(s0 * 64 + bg * 8 + pb)) * 2048
                                       + (dir << 10) + (pq << 8) + j0 + (pe << 2));
        *(float4*)(Gxs + pb * 136 + (pq << 5) + (pe << 2)) = gv;
    }
    // DSMEM peer base addresses for Hb
    uint32_t hb_peer[8];
    {
        uint32_t hb_local = (uint32_t)__cvta_generic_to_shared(Hb);
#pragma unroll
        for (int p = 0; p < 8; ++p)
            asm("mapa.shared::cluster.u32 %0, %1, %2;"
                : "=r"(hb_peer[p]) : "r"(hb_local), "r"(p));
    }
    __syncthreads();

    const int tile = tid >> 3, kid = tid & 7;
    const int r0 = tile << 2;
    const int ujj = tid >> 3, ub = tid & 7;     // update mapping
    float creg = 0.0f;

    for (int t = 0; t < 512; ++t) {
        const int s = dir ? (511 - t) : t;
        const int cur = t & 1, nxt = cur ^ 1;

        // prefetch gx(t+1) into regs (off critical path)
        float4 gv;
        {
            int t2 = (t < 511) ? (t + 1) : t;
            int s2 = dir ? (511 - t2) : t2;
            gv = *(const float4*)(gx + ((size_t)(s2 * 64 + bg * 8 + pb)) * 2048
                                    + (dir << 10) + (pq << 8) + j0 + (pe << 2));
        }

        // dot: 4 rows (r0..r0+3) x 8 batches, k-split 8 (kid owns k = 4kid+32kk)
        float acc[4][8];
#pragma unroll
        for (int i = 0; i < 4; ++i)
#pragma unroll
            for (int j = 0; j < 8; ++j) acc[i][j] = 0.0f;

        const float4* wp0 = (const float4*)(Wsl + (r0 + 0) * 260 + (kid << 2));
        const float4* wp1 = (const float4*)(Wsl + (r0 + 1) * 260 + (kid << 2));
        const float4* wp2 = (const float4*)(Wsl + (r0 + 2) * 260 + (kid << 2));
        const float4* wp3 = (const float4*)(Wsl + (r0 + 3) * 260 + (kid << 2));
        const float4* hp  = (const float4*)(Hb + (cur << 11) + (kid << 2));
#pragma unroll
        for (int kk = 0; kk < 8; ++kk) {
            const int ko = kk << 3;
            float4 w0 = wp0[ko], w1 = wp1[ko], w2 = wp2[ko], w3 = wp3[ko];
#pragma unroll
            for (int j = 0; j < 8; ++j) {
                float4 hv = hp[(j << 6) + ko];
                acc[0][j] = fmaf(w0.x, hv.x, fmaf(w0.y, hv.y, fmaf(w0.z, hv.z, fmaf(w0.w, hv.w, acc[0][j]))));
                acc[1][j] = fmaf(w1.x, hv.x, fmaf(w1.y, hv.y, fmaf(w1.z, hv.z, fmaf(w1.w, hv.w, acc[1][j]))));
                acc[2][j] = fmaf(w2.x, hv.x, fmaf(w2.y, hv.y, fmaf(w2.z, hv.z, fmaf(w2.w, hv.w, acc[2][j]))));
                acc[3][j] = fmaf(w3.x, hv.x, fmaf(w3.y, hv.y, fmaf(w3.z, hv.z, fmaf(w3.w, hv.w, acc[3][j]))));
            }
        }
        // reduce across 8 kid lanes; kid 0 writes Gs[b][row]
#pragma unroll
        for (int i = 0; i < 4; ++i)
#pragma unroll
            for (int j = 0; j < 8; ++j) {
                float v = acc[i][j];
                v += __shfl_xor_sync(0xffffffffu, v, 1);
                v += __shfl_xor_sync(0xffffffffu, v, 2);
                v += __shfl_xor_sync(0xffffffffu, v, 4);
                if (kid == 0) Gs[j * 136 + r0 + i] = v;
            }
        // stage gx(t+1)
        *(float4*)(Gxs + nxt * 1088 + pb * 136 + (pq << 5) + (pe << 2)) = gv;
        __syncthreads();

        // update: thread (ujj, ub) owns h-dim j0+ujj, batch ub
        {
            const float* gsb = Gs + ub * 136;
            const float* gxb = Gxs + cur * 1088 + ub * 136;
            float di = gsb[ujj]      + gxb[ujj];
            float df = gsb[32 + ujj] + gxb[32 + ujj];
            float dg = gsb[64 + ujj] + gxb[64 + ujj];
            float dq = gsb[96 + ujj] + gxb[96 + ujj];
            float c = sigm(df) * creg + sigm(di) * tanhf(dg);
            creg = c;
            float h = sigm(dq) * tanhf(c);
            uint32_t off = (uint32_t)(((nxt << 11) + (ub << 8) + j0 + ujj) << 2);
#pragma unroll
            for (int p = 0; p < 8; ++p)
                asm volatile("st.shared::cluster.f32 [%0], %1;"
                             :: "r"(hb_peer[p] + off), "f"(h) : "memory");
            hout[((size_t)(s * 64 + bg * 8 + ub)) * 512 + (dir << 8) + j0 + ujj] = h;
        }
        asm volatile("barrier.cluster.arrive.aligned;" ::: "memory");
        asm volatile("barrier.cluster.wait.aligned;" ::: "memory");
    }
}

__global__ void score_kernel(const float* __restrict__ wlin,
                             const float* __restrict__ blin,
                             const float* __restrict__ labels,
                             const int* __restrict__ masks,
                             float* __restrict__ outs) {
    int w = blockIdx.x * 8 + (threadIdx.x >> 5);
    int lane = threadIdx.x & 31;
    int s = w >> 6, b = w & 63;
    const float* hp = g_h2 + (size_t)w * 512;
    float acc = 0.0f;
#pragma unroll
    for (int j = lane; j < 256; j += 32)
        acc += 0.5f * (hp[j] + hp[256 + j]) * wlin[j];
#pragma unroll
    for (int d = 16; d; d >>= 1) acc += __shfl_xor_sync(0xffffffffu, acc, d);
    if (lane == 0) {
        float sc = sigm(acc + blin[0]);
        int oi = b * S_ + s;
        outs[oi] = sc;
        float df = sc - labels[oi];
        g_err[oi] = df * df * (float)masks[oi];
    }
}

__global__ void loss_kernel(const int* __restrict__ masks,
                            float* __restrict__ out, int out_size) {
    __shared__ float sr[64];
    int b = threadIdx.x;
    if (b < 64) {
        float se = 0.0f, sm = 0.0f;
        for (int s = 0; s < S_; ++s) {
            se += g_err[b * S_ + s];
            sm += (float)masks[b * S_ + s];
        }
        sr[b] = se / sm;
    }
    __syncthreads();
    if (threadIdx.x == 0 && out_size > M_) {
        float t = 0.0f;
        for (int i = 0; i < 64; ++i) t += sr[i];
        out[M_] = t / 64.0f;
    }
}

extern "C" void kernel_launch(void* const* d_in, const int* in_sizes, int n_in,
                              void* d_out, int out_size) {
    const int*   ids    = (const int*)d_in[0];
    const float* labels = (const float*)d_in[1];
    const int*   masks  = (const int*)d_in[2];
    const float* emb    = (const float*)d_in[3];
    const float* wih0f = (const float*)d_in[4];
    const float* whh0f = (const float*)d_in[5];
    const float* bih0f = (const float*)d_in[6];
    const float* bhh0f = (const float*)d_in[7];
    const float* wih0b = (const float*)d_in[8];
    const float* whh0b = (const float*)d_in[9];
    const float* bih0b = (const float*)d_in[10];
    const float* bhh0b = (const float*)d_in[11];
    const float* wih1f = (const float*)d_in[12];
    const float* whh1f = (const float*)d_in[13];
    const float* bih1f = (const float*)d_in[14];
    const float* bhh1f = (const float*)d_in[15];
    const float* wih1b = (const float*)d_in[16];
    const float* whh1b = (const float*)d_in[17];
    const float* bih1b = (const float*)d_in[18];
    const float* bhh1b = (const float*)d_in[19];
    const float* wlin  = (const float*)d_in[20];
    const float* blin  = (const float*)d_in[21];
    float* out = (float*)d_out;

    static bool attr_done = false;
    if (!attr_done) {
        cudaFuncSetAttribute(lstm_kernel, cudaFuncAttributeMaxDynamicSharedMemorySize,
                             LSTM_SMEM_BYTES);
        attr_done = true;
    }

    gather_kernel<<<M_, 128>>>(ids, emb);
    padw_kernel<<<2048, 128>>>(wih0f, wih0b);

    dim3 gg(16, 256);
    sgemm_kernel<<<gg, 256>>>(0, 0, nullptr, bih0f, bhh0f);
    sgemm_kernel<<<gg, 256>>>(0, 1, nullptr, bih0b, bhh0b);

    lstm_kernel<<<128, 256, LSTM_SMEM_BYTES>>>(0, whh0f, whh0b);

    sgemm_kernel<<<gg, 256>>>(1, 0, wih1f, bih1f, bhh1f);
    sgemm_kernel<<<gg, 256>>>(1, 1, wih1b, bih1b, bhh1b);

    lstm_kernel<<<128, 256, LSTM_SMEM_BYTES>>>(1, whh1f, whh1b);

    score_kernel<<<M_ / 8, 256>>>(wlin, blin, labels, masks, out);
    loss_kernel<<<1, 64>>>(masks, out, out_size);
}